// round 9
// baseline (speedup 1.0000x reference)
#include <cuda_runtime.h>
#include <cstdint>
#include <cstddef>

typedef unsigned long long ull;

// ---------------- constants ----------------
#define BB   256
#define SS   512
#define DD   200
#define HH   256
#define NJ   1024          // 4*H packed gate columns
#define NGRP 16            // batch groups (16 rows each)
#define NCOL 8             // column-group CTAs per batch group (32 hidden cols each)

// ---------------- device scratch ----------------
__device__ float    g_G[134217728];   // [B][S][1024] gate preactivations (x part + bias)
__device__ float    g_Wxp[DD * NJ];   // packed x-weights  [200][1024]
__device__ float    g_Whp[8 * 32768]; // packed h-weights  [colgrp][256][128]
__device__ float    g_biasp[NJ];
__device__ float    g_hbuf[2 * 65536];   // [parity][group][col 256][row 16]
__device__ unsigned g_bar[NGRP];         // per-group monotonic barrier counters

// ---------------- helpers ----------------
__device__ __forceinline__ ull pk2(float lo, float hi) {
    ull r; asm("mov.b64 %0,{%1,%2};" : "=l"(r) : "f"(lo), "f"(hi)); return r;
}
__device__ __forceinline__ void upk2(ull v, float& lo, float& hi) {
    asm("mov.b64 {%0,%1},%2;" : "=f"(lo), "=f"(hi) : "l"(v));
}
__device__ __forceinline__ ull ffma2(ull a, ull b, ull c) {
    ull d; asm("fma.rn.f32x2 %0,%1,%2,%3;" : "=l"(d) : "l"(a), "l"(b), "l"(c)); return d;
}
__device__ __forceinline__ float sigf(float x) {
    return __fdividef(1.0f, 1.0f + __expf(-x));
}
__device__ __forceinline__ float tanhfast(float x) {
    return __fdividef(2.0f, 1.0f + __expf(-2.0f * x)) - 1.0f;
}
__device__ __forceinline__ unsigned ldacq(const unsigned* p) {
    unsigned v;
    asm volatile("ld.global.acquire.gpu.u32 %0,[%1];" : "=r"(v) : "l"(p) : "memory");
    return v;
}
__device__ __forceinline__ void red_release(unsigned* p) {
    asm volatile("red.release.gpu.global.add.u32 [%0], %1;" :: "l"(p), "r"(1u) : "memory");
}

// ---------------- kernel 0: pack weights ----------------
// j = g*128 + c*4 + gate  (g: col group 0..7, c: col-in-group 0..31, gate: i,f,o,z)
__global__ void k_pack(const float* __restrict__ Wi, const float* __restrict__ Wf,
                       const float* __restrict__ Wo, const float* __restrict__ Wz,
                       const float* __restrict__ bi, const float* __restrict__ bf,
                       const float* __restrict__ bo, const float* __restrict__ bz) {
    int idx = blockIdx.x * blockDim.x + threadIdx.x;
    if (idx < 456 * NJ) {
        int k = idx >> 10;
        int j = idx & (NJ - 1);
        int gate = j & 3;
        int c    = (j >> 2) & 31;
        int g    = j >> 7;
        int col  = g * 32 + c;
        const float* W = (gate == 0) ? Wi : (gate == 1) ? Wf : (gate == 2) ? Wo : Wz;
        float v = W[k * HH + col];
        if (k < DD) g_Wxp[k * NJ + j] = v;
        else        g_Whp[g * 32768 + (k - DD) * 128 + (j & 127)] = v;
    }
    if (idx < NJ) {
        int gate = idx & 3;
        int c    = (idx >> 2) & 31;
        int g    = idx >> 7;
        int col  = g * 32 + c;
        const float* bb = (gate == 0) ? bi : (gate == 1) ? bf : (gate == 2) ? bo : bz;
        g_biasp[idx] = bb[col];
    }
}

// ---------------- kernel 1: reset mailbox + barrier counters ----------------
__global__ void k_reset() {
    int i = blockIdx.x * blockDim.x + threadIdx.x;
    if (i < 2 * 65536) g_hbuf[i] = 0.0f;
    if (i < NGRP)      g_bar[i] = 0u;
}

// ---------------- kernel 2: G = X @ Wxp + bias ----------------
// m = b*512 + s. Tile 128x128, K-chunk 8, double-buffered, B dup (b,b).
// Per kk per thread: 6x LDS.128 + 32x ffma2 -> fma-pipe-bound (issue slack 40%).
#define G1_BM 128
#define G1_BN 128
#define G1_BK 8
__global__ void __launch_bounds__(256) k_gemm1(const float* __restrict__ x) {
    __shared__ __align__(16) float As[2][G1_BK][G1_BM];       // [k][row]
    __shared__ __align__(16) float Bs[2][G1_BK][G1_BN * 2];   // [k][col dup pairs]

    int tid = threadIdx.x;
    int m0 = blockIdx.y * G1_BM;
    int n0 = blockIdx.x * G1_BN;

    // A loader: 2 threads per row, each a float4 of k
    int arow = tid >> 1;
    int akq  = (tid & 1) * 4;
    const float* aptr = x + (size_t)(m0 + arow) * DD + akq;

    // B loader: 32 threads per k-row, float4 (4 cols) each -> 2 dup float4 stores
    int bkk = tid >> 5;
    int bc4 = (tid & 31) * 4;
    const float* bptr = g_Wxp + (size_t)bkk * NJ + n0 + bc4;

    int tx = tid & 15;   // 8 n-cols
    int ty = tid >> 4;   // 8 m-rows

    ull acc[4][8];
#pragma unroll
    for (int i = 0; i < 4; ++i)
#pragma unroll
        for (int j = 0; j < 8; ++j) acc[i][j] = 0ull;

    // prologue
    float4 av = *(const float4*)aptr;
    float4 bv = *(const float4*)bptr;
    As[0][akq + 0][arow] = av.x;
    As[0][akq + 1][arow] = av.y;
    As[0][akq + 2][arow] = av.z;
    As[0][akq + 3][arow] = av.w;
    *(float4*)&Bs[0][bkk][bc4 * 2]     = make_float4(bv.x, bv.x, bv.y, bv.y);
    *(float4*)&Bs[0][bkk][bc4 * 2 + 4] = make_float4(bv.z, bv.z, bv.w, bv.w);

    for (int kc = 0; kc < 25; ++kc) {
        __syncthreads();
        int cur = kc & 1;
        if (kc < 24) {
            av = *(const float4*)(aptr + (kc + 1) * G1_BK);
            bv = *(const float4*)(bptr + (size_t)(kc + 1) * G1_BK * NJ);
        }
#pragma unroll
        for (int kk = 0; kk < G1_BK; ++kk) {
            const ulonglong2* ap2 = (const ulonglong2*)&As[cur][kk][ty * 8];
            ulonglong2 aA = ap2[0], aB = ap2[1];   // row pairs (0,1),(2,3),(4,5),(6,7)
            const ulonglong2* bp2 = (const ulonglong2*)&Bs[cur][kk][tx * 16];
            ulonglong2 b0 = bp2[0], b1 = bp2[1], b2 = bp2[2], b3 = bp2[3];
            ull ar0 = aA.x, ar1 = aA.y, ar2 = aB.x, ar3 = aB.y;
            acc[0][0] = ffma2(ar0, b0.x, acc[0][0]); acc[0][1] = ffma2(ar0, b0.y, acc[0][1]);
            acc[0][2] = ffma2(ar0, b1.x, acc[0][2]); acc[0][3] = ffma2(ar0, b1.y, acc[0][3]);
            acc[0][4] = ffma2(ar0, b2.x, acc[0][4]); acc[0][5] = ffma2(ar0, b2.y, acc[0][5]);
            acc[0][6] = ffma2(ar0, b3.x, acc[0][6]); acc[0][7] = ffma2(ar0, b3.y, acc[0][7]);
            acc[1][0] = ffma2(ar1, b0.x, acc[1][0]); acc[1][1] = ffma2(ar1, b0.y, acc[1][1]);
            acc[1][2] = ffma2(ar1, b1.x, acc[1][2]); acc[1][3] = ffma2(ar1, b1.y, acc[1][3]);
            acc[1][4] = ffma2(ar1, b2.x, acc[1][4]); acc[1][5] = ffma2(ar1, b2.y, acc[1][5]);
            acc[1][6] = ffma2(ar1, b3.x, acc[1][6]); acc[1][7] = ffma2(ar1, b3.y, acc[1][7]);
            acc[2][0] = ffma2(ar2, b0.x, acc[2][0]); acc[2][1] = ffma2(ar2, b0.y, acc[2][1]);
            acc[2][2] = ffma2(ar2, b1.x, acc[2][2]); acc[2][3] = ffma2(ar2, b1.y, acc[2][3]);
            acc[2][4] = ffma2(ar2, b2.x, acc[2][4]); acc[2][5] = ffma2(ar2, b2.y, acc[2][5]);
            acc[2][6] = ffma2(ar2, b3.x, acc[2][6]); acc[2][7] = ffma2(ar2, b3.y, acc[2][7]);
            acc[3][0] = ffma2(ar3, b0.x, acc[3][0]); acc[3][1] = ffma2(ar3, b0.y, acc[3][1]);
            acc[3][2] = ffma2(ar3, b1.x, acc[3][2]); acc[3][3] = ffma2(ar3, b1.y, acc[3][3]);
            acc[3][4] = ffma2(ar3, b2.x, acc[3][4]); acc[3][5] = ffma2(ar3, b2.y, acc[3][5]);
            acc[3][6] = ffma2(ar3, b3.x, acc[3][6]); acc[3][7] = ffma2(ar3, b3.y, acc[3][7]);
        }
        if (kc < 24) {
            int nxt = cur ^ 1;
            As[nxt][akq + 0][arow] = av.x;
            As[nxt][akq + 1][arow] = av.y;
            As[nxt][akq + 2][arow] = av.z;
            As[nxt][akq + 3][arow] = av.w;
            *(float4*)&Bs[nxt][bkk][bc4 * 2]     = make_float4(bv.x, bv.x, bv.y, bv.y);
            *(float4*)&Bs[nxt][bkk][bc4 * 2 + 4] = make_float4(bv.z, bv.z, bv.w, bv.w);
        }
    }

    float4 bias4a = *(const float4*)(g_biasp + n0 + tx * 8);
    float4 bias4b = *(const float4*)(g_biasp + n0 + tx * 8 + 4);
#pragma unroll
    for (int rp = 0; rp < 4; ++rp) {
        float4 e0, e1, o0, o1;
        upk2(acc[rp][0], e0.x, o0.x); upk2(acc[rp][1], e0.y, o0.y);
        upk2(acc[rp][2], e0.z, o0.z); upk2(acc[rp][3], e0.w, o0.w);
        upk2(acc[rp][4], e1.x, o1.x); upk2(acc[rp][5], e1.y, o1.y);
        upk2(acc[rp][6], e1.z, o1.z); upk2(acc[rp][7], e1.w, o1.w);
        e0.x += bias4a.x; e0.y += bias4a.y; e0.z += bias4a.z; e0.w += bias4a.w;
        e1.x += bias4b.x; e1.y += bias4b.y; e1.z += bias4b.z; e1.w += bias4b.w;
        o0.x += bias4a.x; o0.y += bias4a.y; o0.z += bias4a.z; o0.w += bias4a.w;
        o1.x += bias4b.x; o1.y += bias4b.y; o1.z += bias4b.z; o1.w += bias4b.w;
        size_t mrow = (size_t)m0 + ty * 8 + rp * 2;
        __stcs((float4*)(g_G + mrow * NJ + n0 + tx * 8), e0);
        __stcs((float4*)(g_G + mrow * NJ + n0 + tx * 8 + 4), e1);
        __stcs((float4*)(g_G + (mrow + 1) * NJ + n0 + tx * 8), o0);
        __stcs((float4*)(g_G + (mrow + 1) * NJ + n0 + tx * 8 + 4), o1);
    }
}

// ---------------- kernel 3: persistent recurrence (EXACT R4, proven 5131.6) ----------------
#define REC_SMEM_BYTES (131072 + 32768 + 32768)
__global__ void __launch_bounds__(256, 1) k_rec(const float* __restrict__ mask,
                                                float* __restrict__ out) {
    extern __shared__ __align__(16) float sm[];
    float*  Ws = sm;                         // [256 k][128 j]
    float4* hs = (float4*)(sm + 32768);      // [256 k][8 rp] dup pairs, slot rp^(k&7)
    float*  ms = sm + 32768 + 8192;          // [512 s][16 r] mask transposed

    int tid = threadIdx.x;
    int grp = blockIdx.x >> 3;
    int g   = blockIdx.x & 7;
    int rp  = tid & 7;    // row pair: rows 2rp, 2rp+1
    int cq  = tid >> 3;   // hidden col in slice 0..31

    // preload weight slice (once for all 512 steps)
    {
        const float4* wsrc = (const float4*)(g_Whp + (size_t)g * 32768);
        float4* wdst = (float4*)Ws;
        for (int i = tid; i < 8192; i += 256) wdst[i] = wsrc[i];
    }
    // mask transpose: ms[s*16 + r]
    for (int i = tid; i < 8192; i += 256) {
        int r = i >> 9, s = i & 511;
        ms[s * 16 + r] = mask[(size_t)(grp * 16 + r) * SS + s];
    }
    __syncthreads();

    int b0 = grp * 16 + rp * 2;
    float c0 = 0.f, c1 = 0.f, sum0 = 0.f, sum1 = 0.f, msum0 = 0.f, msum1 = 0.f;
    const float* gbase = g_G + (size_t)b0 * SS * NJ + g * 128 + cq * 4;
    unsigned* barp = &g_bar[grp];
    int sw = tid & 7;     // gather-store swizzle (thread tid owns hidden col k=tid)

    for (int s = 0; s < SS; ++s) {
        // prefetch this step's x-gate preactivations (independent of h)
        float4 ga = __ldcs((const float4*)(gbase + (size_t)s * NJ));
        float4 gb = __ldcs((const float4*)(gbase + (size_t)SS * NJ + (size_t)s * NJ));
        float2 mv = *(const float2*)&ms[s * 16 + rp * 2];

        // wait for all 8 CTAs of this group to have published step s's h
        if (s > 0) {
            if (tid == 0) {
                unsigned tgt = 8u * (unsigned)s;
                while (ldacq(barp) < tgt) {}
            }
            __syncthreads();
        }

        // gather h[s]: thread owns hidden col k = tid, all 16 rows; store dup float4
        {
            const float4* src =
                (const float4*)(g_hbuf + ((size_t)(s & 1)) * 65536 + (size_t)grp * 4096) +
                tid * 4;
            float4 v0 = __ldcg(src + 0);
            float4 v1 = __ldcg(src + 1);
            float4 v2 = __ldcg(src + 2);
            float4 v3 = __ldcg(src + 3);
            float4* hd = hs + tid * 8;
            hd[0 ^ sw] = make_float4(v0.x, v0.x, v0.y, v0.y);
            hd[1 ^ sw] = make_float4(v0.z, v0.z, v0.w, v0.w);
            hd[2 ^ sw] = make_float4(v1.x, v1.x, v1.y, v1.y);
            hd[3 ^ sw] = make_float4(v1.z, v1.z, v1.w, v1.w);
            hd[4 ^ sw] = make_float4(v2.x, v2.x, v2.y, v2.y);
            hd[5 ^ sw] = make_float4(v2.z, v2.z, v2.w, v2.w);
            hd[6 ^ sw] = make_float4(v3.x, v3.x, v3.y, v3.y);
            hd[7 ^ sw] = make_float4(v3.z, v3.z, v3.w, v3.w);
        }
        __syncthreads();

        // gates = G + h @ Wh : 2 rows x 4 gate cols per thread
        ull a00 = pk2(ga.x, ga.y), a01 = pk2(ga.z, ga.w);
        ull a10 = pk2(gb.x, gb.y), a11 = pk2(gb.z, gb.w);
        const ulonglong2* wq = (const ulonglong2*)Ws + cq;    // +32 per k
        const ulonglong2* hq = (const ulonglong2*)hs;         // +8 per k, slot rp^(k&7)
#pragma unroll 8
        for (int k = 0; k < HH; ++k) {
            ulonglong2 w = wq[k * 32];                 // (wi,wf),(wo,wz)
            ulonglong2 h = hq[k * 8 + (rp ^ (k & 7))]; // (h0,h0),(h1,h1)
            a00 = ffma2(h.x, w.x, a00); a01 = ffma2(h.x, w.y, a01);
            a10 = ffma2(h.y, w.x, a10); a11 = ffma2(h.y, w.y, a11);
        }

        // nonlinearity + state update (gate order i,f,o,z)
        float ai0, af0, ao0, az0, ai1, af1, ao1, az1;
        upk2(a00, ai0, af0); upk2(a01, ao0, az0);
        upk2(a10, ai1, af1); upk2(a11, ao1, az1);
        float i0 = sigf(ai0), f0 = sigf(af0), o0 = sigf(ao0), z0 = tanhfast(az0);
        c0 = i0 * z0 + f0 * c0;
        float h0 = o0 * tanhfast(c0);
        float i1 = sigf(ai1), f1 = sigf(af1), o1 = sigf(ao1), z1 = tanhfast(az1);
        c1 = i1 * z1 + f1 * c1;
        float h1 = o1 * tanhfast(c1);
        sum0 += h0 * mv.x; msum0 += mv.x;
        sum1 += h1 * mv.y; msum1 += mv.y;

        // publish h[s+1]: [col][row] layout, one stcg.64
        float2 hv; hv.x = h0; hv.y = h1;
        __stcg((float2*)(g_hbuf + ((size_t)((s + 1) & 1)) * 65536 + (size_t)grp * 4096 +
                         (size_t)(g * 32 + cq) * 16 + rp * 2),
               hv);
        __syncthreads();
        if (tid == 0) red_release(barp);
    }

    int hcol = g * 32 + cq;
    out[(size_t)b0 * HH + hcol]       = sum0 * __fdividef(1.0f, msum0);
    out[(size_t)(b0 + 1) * HH + hcol] = sum1 * __fdividef(1.0f, msum1);
}

// ---------------- launcher ----------------
extern "C" void kernel_launch(void* const* d_in, const int* in_sizes, int n_in,
                              void* d_out, int out_size) {
    const float* x    = (const float*)d_in[0];
    const float* mask = (const float*)d_in[1];
    const float* Wi   = (const float*)d_in[2];
    const float* bi   = (const float*)d_in[3];
    const float* Wf   = (const float*)d_in[4];
    const float* bf   = (const float*)d_in[5];
    const float* Wo   = (const float*)d_in[6];
    const float* bo   = (const float*)d_in[7];
    const float* Wz   = (const float*)d_in[8];
    const float* bz   = (const float*)d_in[9];
    float* out = (float*)d_out;

    cudaFuncSetAttribute(k_rec, cudaFuncAttributeMaxDynamicSharedMemorySize,
                         REC_SMEM_BYTES);

    k_pack<<<(456 * NJ + 255) / 256, 256>>>(Wi, Wf, Wo, Wz, bi, bf, bo, bz);
    k_reset<<<512, 256>>>();
    dim3 g1(NJ / G1_BN, (BB * SS) / G1_BM);
    k_gemm1<<<g1, 256>>>(x);
    k_rec<<<NGRP * NCOL, 256, REC_SMEM_BYTES>>>(mask, out);
}

// round 11
// speedup vs baseline: 1.7073x; 1.7073x over previous
#include <cuda_runtime.h>
#include <cstdint>
#include <cstddef>

typedef unsigned long long ull;

// ---------------- constants ----------------
#define BB   256
#define SS   512
#define DD   200
#define HH   256
#define NJ   1024          // 4*H packed gate columns
#define NGRP 16            // batch groups (16 rows each)
#define NCOL 8             // column-group CTAs per batch group (32 hidden cols each)

// ---------------- device scratch ----------------
__device__ float    g_G[134217728];   // [B][S][1024] gate preactivations (x part + bias)
__device__ float    g_Wxp[DD * NJ];   // packed x-weights  [200][1024]
__device__ float    g_Whp[8 * 32768]; // packed h-weights  [colgrp][256][128]
__device__ float    g_biasp[NJ];
__device__ float    g_hbuf[2 * 65536];   // [parity][group][col 256][row 16]
__device__ unsigned g_bar[NGRP];         // per-group monotonic barrier counters

// ---------------- helpers ----------------
__device__ __forceinline__ ull pk2(float lo, float hi) {
    ull r; asm("mov.b64 %0,{%1,%2};" : "=l"(r) : "f"(lo), "f"(hi)); return r;
}
__device__ __forceinline__ void upk2(ull v, float& lo, float& hi) {
    asm("mov.b64 {%0,%1},%2;" : "=f"(lo), "=f"(hi) : "l"(v));
}
__device__ __forceinline__ ull ffma2(ull a, ull b, ull c) {
    ull d; asm("fma.rn.f32x2 %0,%1,%2,%3;" : "=l"(d) : "l"(a), "l"(b), "l"(c)); return d;
}
__device__ __forceinline__ float sigf(float x) {
    return __fdividef(1.0f, 1.0f + __expf(-x));
}
__device__ __forceinline__ float tanhfast(float x) {
    return __fdividef(2.0f, 1.0f + __expf(-2.0f * x)) - 1.0f;
}
__device__ __forceinline__ unsigned ldacq(const unsigned* p) {
    unsigned v;
    asm volatile("ld.global.acquire.gpu.u32 %0,[%1];" : "=r"(v) : "l"(p) : "memory");
    return v;
}
__device__ __forceinline__ void red_release(unsigned* p) {
    asm volatile("red.release.gpu.global.add.u32 [%0], %1;" :: "l"(p), "r"(1u) : "memory");
}

// ---------------- kernel 0: pack weights ----------------
// j = g*128 + c*4 + gate  (g: col group 0..7, c: col-in-group 0..31, gate: i,f,o,z)
__global__ void k_pack(const float* __restrict__ Wi, const float* __restrict__ Wf,
                       const float* __restrict__ Wo, const float* __restrict__ Wz,
                       const float* __restrict__ bi, const float* __restrict__ bf,
                       const float* __restrict__ bo, const float* __restrict__ bz) {
    int idx = blockIdx.x * blockDim.x + threadIdx.x;
    if (idx < 456 * NJ) {
        int k = idx >> 10;
        int j = idx & (NJ - 1);
        int gate = j & 3;
        int c    = (j >> 2) & 31;
        int g    = j >> 7;
        int col  = g * 32 + c;
        const float* W = (gate == 0) ? Wi : (gate == 1) ? Wf : (gate == 2) ? Wo : Wz;
        float v = W[k * HH + col];
        if (k < DD) g_Wxp[k * NJ + j] = v;
        else        g_Whp[g * 32768 + (k - DD) * 128 + (j & 127)] = v;
    }
    if (idx < NJ) {
        int gate = idx & 3;
        int c    = (idx >> 2) & 31;
        int g    = idx >> 7;
        int col  = g * 32 + c;
        const float* bb = (gate == 0) ? bi : (gate == 1) ? bf : (gate == 2) ? bo : bz;
        g_biasp[idx] = bb[col];
    }
}

// ---------------- kernel 1: reset mailbox + barrier counters ----------------
__global__ void k_reset() {
    int i = blockIdx.x * blockDim.x + threadIdx.x;
    if (i < 2 * 65536) g_hbuf[i] = 0.0f;
    if (i < NGRP)      g_bar[i] = 0u;
}

// ---------------- kernel 2: G = X @ Wxp + bias (EXACT R4 version) ----------------
#define G1_BM 128
#define G1_BN 64
#define G1_BK 8
__global__ void __launch_bounds__(256) k_gemm1(const float* __restrict__ x) {
    __shared__ __align__(16) float As[2][G1_BK][G1_BM];
    __shared__ __align__(16) float Bs[2][G1_BK][G1_BN];

    int tid = threadIdx.x;
    int m0 = blockIdx.y * G1_BM;
    int n0 = blockIdx.x * G1_BN;

    int arow = tid >> 1;
    int akq  = (tid & 1) * 4;
    const float* aptr = x + (size_t)(m0 + arow) * DD + akq;

    int bkk = tid >> 5;
    int bn  = (tid & 31) * 2;
    const float* bptr = g_Wxp + (size_t)bkk * NJ + n0 + bn;

    int tx = tid & 15;   // 4 n-cols
    int ty = tid >> 4;   // 8 m-rows

    ull acc[4][4];
#pragma unroll
    for (int i = 0; i < 4; ++i)
#pragma unroll
        for (int j = 0; j < 4; ++j) acc[i][j] = 0ull;

    float4 av = *(const float4*)aptr;
    float2 bv = *(const float2*)bptr;
    As[0][akq + 0][arow] = av.x;
    As[0][akq + 1][arow] = av.y;
    As[0][akq + 2][arow] = av.z;
    As[0][akq + 3][arow] = av.w;
    *(float2*)&Bs[0][bkk][bn] = bv;

    for (int kc = 0; kc < 25; ++kc) {
        __syncthreads();
        int cur = kc & 1;
        if (kc < 24) {
            av = *(const float4*)(aptr + (kc + 1) * G1_BK);
            bv = *(const float2*)(bptr + (size_t)(kc + 1) * G1_BK * NJ);
        }
#pragma unroll
        for (int kk = 0; kk < G1_BK; ++kk) {
            const ull* ap2 = (const ull*)&As[cur][kk][ty * 8];
            ull A0 = ap2[0], A1 = ap2[1], A2 = ap2[2], A3 = ap2[3];
            float4 b4 = *(const float4*)&Bs[cur][kk][tx * 4];
            ull B0 = pk2(b4.x, b4.x), B1 = pk2(b4.y, b4.y);
            ull B2 = pk2(b4.z, b4.z), B3 = pk2(b4.w, b4.w);
            acc[0][0] = ffma2(A0, B0, acc[0][0]); acc[0][1] = ffma2(A0, B1, acc[0][1]);
            acc[0][2] = ffma2(A0, B2, acc[0][2]); acc[0][3] = ffma2(A0, B3, acc[0][3]);
            acc[1][0] = ffma2(A1, B0, acc[1][0]); acc[1][1] = ffma2(A1, B1, acc[1][1]);
            acc[1][2] = ffma2(A1, B2, acc[1][2]); acc[1][3] = ffma2(A1, B3, acc[1][3]);
            acc[2][0] = ffma2(A2, B0, acc[2][0]); acc[2][1] = ffma2(A2, B1, acc[2][1]);
            acc[2][2] = ffma2(A2, B2, acc[2][2]); acc[2][3] = ffma2(A2, B3, acc[2][3]);
            acc[3][0] = ffma2(A3, B0, acc[3][0]); acc[3][1] = ffma2(A3, B1, acc[3][1]);
            acc[3][2] = ffma2(A3, B2, acc[3][2]); acc[3][3] = ffma2(A3, B3, acc[3][3]);
        }
        if (kc < 24) {
            int nxt = cur ^ 1;
            As[nxt][akq + 0][arow] = av.x;
            As[nxt][akq + 1][arow] = av.y;
            As[nxt][akq + 2][arow] = av.z;
            As[nxt][akq + 3][arow] = av.w;
            *(float2*)&Bs[nxt][bkk][bn] = bv;
        }
    }

    float4 bias4 = *(const float4*)(g_biasp + n0 + tx * 4);
#pragma unroll
    for (int rp = 0; rp < 4; ++rp) {
        float4 r0, r1;
        upk2(acc[rp][0], r0.x, r1.x);
        upk2(acc[rp][1], r0.y, r1.y);
        upk2(acc[rp][2], r0.z, r1.z);
        upk2(acc[rp][3], r0.w, r1.w);
        r0.x += bias4.x; r0.y += bias4.y; r0.z += bias4.z; r0.w += bias4.w;
        r1.x += bias4.x; r1.y += bias4.y; r1.z += bias4.z; r1.w += bias4.w;
        size_t mrow = (size_t)m0 + ty * 8 + rp * 2;
        __stcs((float4*)(g_G + mrow * NJ + n0 + tx * 4), r0);
        __stcs((float4*)(g_G + (mrow + 1) * NJ + n0 + tx * 4), r1);
    }
}

// ---------------- kernel 3: persistent recurrence ----------------
// R4 base; ONLY change: h staged as (hr0[2k],hr1[2k],hr0[2k+1],hr1[2k+1]) float4
// -> matvec inner = 3 LDS.128 per 2 k (was 4), crossbar 4096->3072 wf/step.
// Weight row k is 128 floats = 32 ulonglong2: k=2k2 -> wq[k2*64], k=2k2+1 -> wq[k2*64+32].
// smem: Ws 131072B + hs 16384B + ms 32768B
#define REC_SMEM_BYTES (131072 + 16384 + 32768)
__global__ void __launch_bounds__(256, 1) k_rec(const float* __restrict__ mask,
                                                float* __restrict__ out) {
    extern __shared__ __align__(16) float sm[];
    float*  Ws = sm;                         // [256 k][128 j]
    float4* hs = (float4*)(sm + 32768);      // [128 k2][8 rp], slot rp^(k2&7)
    float*  ms = sm + 32768 + 4096;          // [512 s][16 r] mask transposed

    int tid = threadIdx.x;
    int grp = blockIdx.x >> 3;
    int g   = blockIdx.x & 7;
    int rp  = tid & 7;    // row pair: rows 2rp, 2rp+1
    int cq  = tid >> 3;   // hidden col in slice 0..31

    // preload weight slice (once for all 512 steps)
    {
        const float4* wsrc = (const float4*)(g_Whp + (size_t)g * 32768);
        float4* wdst = (float4*)Ws;
        for (int i = tid; i < 8192; i += 256) wdst[i] = wsrc[i];
    }
    // mask transpose: ms[s*16 + r]
    for (int i = tid; i < 8192; i += 256) {
        int r = i >> 9, s = i & 511;
        ms[s * 16 + r] = mask[(size_t)(grp * 16 + r) * SS + s];
    }
    __syncthreads();

    int b0 = grp * 16 + rp * 2;
    float c0 = 0.f, c1 = 0.f, sum0 = 0.f, sum1 = 0.f, msum0 = 0.f, msum1 = 0.f;
    const float* gbase = g_G + (size_t)b0 * SS * NJ + g * 128 + cq * 4;
    unsigned* barp = &g_bar[grp];
    int gsw = tid & 7;    // gather-store swizzle (thread tid<128 owns cols 2tid,2tid+1)

    for (int s = 0; s < SS; ++s) {
        // prefetch this step's x-gate preactivations (independent of h)
        float4 ga = __ldcs((const float4*)(gbase + (size_t)s * NJ));
        float4 gb = __ldcs((const float4*)(gbase + (size_t)SS * NJ + (size_t)s * NJ));
        float2 mv = *(const float2*)&ms[s * 16 + rp * 2];

        // wait for all 8 CTAs of this group to have published step s's h
        if (s > 0) {
            if (tid == 0) {
                unsigned tgt = 8u * (unsigned)s;
                while (ldacq(barp) < tgt) {}
            }
            __syncthreads();
        }

        // gather h[s]: thread t<128 owns cols 2t,2t+1 (128B contiguous LDG),
        // repack into (hr0[2t],hr1[2t],hr0[2t+1],hr1[2t+1]) per row pair, swizzled.
        if (tid < 128) {
            const float4* src =
                (const float4*)(g_hbuf + ((size_t)(s & 1)) * 65536 + (size_t)grp * 4096) +
                tid * 8;
            float4 v0 = __ldcg(src + 0);   // col 2t rows 0-3
            float4 v1 = __ldcg(src + 1);   // col 2t rows 4-7
            float4 v2 = __ldcg(src + 2);   // col 2t rows 8-11
            float4 v3 = __ldcg(src + 3);   // col 2t rows 12-15
            float4 u0 = __ldcg(src + 4);   // col 2t+1 rows 0-3
            float4 u1 = __ldcg(src + 5);
            float4 u2 = __ldcg(src + 6);
            float4 u3 = __ldcg(src + 7);
            float4* hd = hs + tid * 8;
            hd[0 ^ gsw] = make_float4(v0.x, v0.y, u0.x, u0.y);   // rp=0: rows 0,1
            hd[1 ^ gsw] = make_float4(v0.z, v0.w, u0.z, u0.w);   // rp=1: rows 2,3
            hd[2 ^ gsw] = make_float4(v1.x, v1.y, u1.x, u1.y);
            hd[3 ^ gsw] = make_float4(v1.z, v1.w, u1.z, u1.w);
            hd[4 ^ gsw] = make_float4(v2.x, v2.y, u2.x, u2.y);
            hd[5 ^ gsw] = make_float4(v2.z, v2.w, u2.z, u2.w);
            hd[6 ^ gsw] = make_float4(v3.x, v3.y, u3.x, u3.y);
            hd[7 ^ gsw] = make_float4(v3.z, v3.w, u3.z, u3.w);
        }
        __syncthreads();

        // gates = G + h @ Wh : 2 rows x 4 gate cols per thread, 2 k per iter
        ull a00 = pk2(ga.x, ga.y), a01 = pk2(ga.z, ga.w);
        ull a10 = pk2(gb.x, gb.y), a11 = pk2(gb.z, gb.w);
        const ulonglong2* wq = (const ulonglong2*)Ws + cq;    // row k at +k*32
        const float4* hq = hs;                                // +8 per 2k, slot rp^(k2&7)
#pragma unroll 8
        for (int k2 = 0; k2 < 128; ++k2) {
            ulonglong2 w0 = wq[k2 * 64];        // k=2k2:   (wi,wf),(wo,wz)
            ulonglong2 w1 = wq[k2 * 64 + 32];   // k=2k2+1
            float4 h4 = hq[k2 * 8 + (rp ^ (k2 & 7))];
            ull ha0 = pk2(h4.x, h4.x), hb0 = pk2(h4.y, h4.y);
            ull ha1 = pk2(h4.z, h4.z), hb1 = pk2(h4.w, h4.w);
            a00 = ffma2(ha0, w0.x, a00); a01 = ffma2(ha0, w0.y, a01);
            a10 = ffma2(hb0, w0.x, a10); a11 = ffma2(hb0, w0.y, a11);
            a00 = ffma2(ha1, w1.x, a00); a01 = ffma2(ha1, w1.y, a01);
            a10 = ffma2(hb1, w1.x, a10); a11 = ffma2(hb1, w1.y, a11);
        }

        // nonlinearity + state update (gate order i,f,o,z)
        float ai0, af0, ao0, az0, ai1, af1, ao1, az1;
        upk2(a00, ai0, af0); upk2(a01, ao0, az0);
        upk2(a10, ai1, af1); upk2(a11, ao1, az1);
        float i0 = sigf(ai0), f0 = sigf(af0), o0 = sigf(ao0), z0 = tanhfast(az0);
        c0 = i0 * z0 + f0 * c0;
        float h0 = o0 * tanhfast(c0);
        float i1 = sigf(ai1), f1 = sigf(af1), o1 = sigf(ao1), z1 = tanhfast(az1);
        c1 = i1 * z1 + f1 * c1;
        float h1 = o1 * tanhfast(c1);
        sum0 += h0 * mv.x; msum0 += mv.x;
        sum1 += h1 * mv.y; msum1 += mv.y;

        // publish h[s+1]: [col][row] layout, one stcg.64
        float2 hv; hv.x = h0; hv.y = h1;
        __stcg((float2*)(g_hbuf + ((size_t)((s + 1) & 1)) * 65536 + (size_t)grp * 4096 +
                         (size_t)(g * 32 + cq) * 16 + rp * 2),
               hv);
        __syncthreads();
        if (tid == 0) red_release(barp);
    }

    int hcol = g * 32 + cq;
    out[(size_t)b0 * HH + hcol]       = sum0 * __fdividef(1.0f, msum0);
    out[(size_t)(b0 + 1) * HH + hcol] = sum1 * __fdividef(1.0f, msum1);
}

// ---------------- launcher ----------------
extern "C" void kernel_launch(void* const* d_in, const int* in_sizes, int n_in,
                              void* d_out, int out_size) {
    const float* x    = (const float*)d_in[0];
    const float* mask = (const float*)d_in[1];
    const float* Wi   = (const float*)d_in[2];
    const float* bi   = (const float*)d_in[3];
    const float* Wf   = (const float*)d_in[4];
    const float* bf   = (const float*)d_in[5];
    const float* Wo   = (const float*)d_in[6];
    const float* bo   = (const float*)d_in[7];
    const float* Wz   = (const float*)d_in[8];
    const float* bz   = (const float*)d_in[9];
    float* out = (float*)d_out;

    cudaFuncSetAttribute(k_rec, cudaFuncAttributeMaxDynamicSharedMemorySize,
                         REC_SMEM_BYTES);

    k_pack<<<(456 * NJ + 255) / 256, 256>>>(Wi, Wf, Wo, Wz, bi, bf, bo, bz);
    k_reset<<<512, 256>>>();
    dim3 g1(NJ / G1_BN, (BB * SS) / G1_BM);
    k_gemm1<<<g1, 256>>>(x);
    k_rec<<<NGRP * NCOL, 256, REC_SMEM_BYTES>>>(mask, out);
}

// round 12
// speedup vs baseline: 1.7486x; 1.0242x over previous
#include <cuda_runtime.h>
#include <cstdint>
#include <cstddef>

typedef unsigned long long ull;

// ---------------- constants ----------------
#define BB   256
#define SS   512
#define DD   200
#define HH   256
#define NJ   1024          // 4*H packed gate columns
#define NGRP 16            // batch groups (16 rows each)
#define NCOL 8             // column-group CTAs per batch group (32 hidden cols each)

// ---------------- device scratch ----------------
__device__ float    g_G[134217728];   // [B][S][1024] gate preactivations (x part + bias)
__device__ float    g_Wxp[DD * NJ];   // packed x-weights  [200][1024]
__device__ float    g_Whp[8 * 32768]; // packed h-weights  [colgrp][256][128]
__device__ float    g_biasp[NJ];
__device__ float    g_hbuf[2 * 65536];   // [parity][group][col 256][row 16]
__device__ ull      g_flags[32];         // [group][word]: 4x16-bit producer counters each

// ---------------- helpers ----------------
__device__ __forceinline__ ull pk2(float lo, float hi) {
    ull r; asm("mov.b64 %0,{%1,%2};" : "=l"(r) : "f"(lo), "f"(hi)); return r;
}
__device__ __forceinline__ void upk2(ull v, float& lo, float& hi) {
    asm("mov.b64 {%0,%1},%2;" : "=f"(lo), "=f"(hi) : "l"(v));
}
__device__ __forceinline__ ull ffma2(ull a, ull b, ull c) {
    ull d; asm("fma.rn.f32x2 %0,%1,%2,%3;" : "=l"(d) : "l"(a), "l"(b), "l"(c)); return d;
}
__device__ __forceinline__ float sigf(float x) {
    return __fdividef(1.0f, 1.0f + __expf(-x));
}
__device__ __forceinline__ float tanhfast(float x) {
    return __fdividef(2.0f, 1.0f + __expf(-2.0f * x)) - 1.0f;
}
__device__ __forceinline__ ull ldacq64(const ull* p) {
    ull v;
    asm volatile("ld.global.acquire.gpu.u64 %0,[%1];" : "=l"(v) : "l"(p) : "memory");
    return v;
}
__device__ __forceinline__ void red_release64(ull* p, ull v) {
    asm volatile("red.release.gpu.global.add.u64 [%0], %1;" :: "l"(p), "l"(v) : "memory");
}

// ---------------- kernel 0: pack weights ----------------
// j = g*128 + c*4 + gate  (g: col group 0..7, c: col-in-group 0..31, gate: i,f,o,z)
__global__ void k_pack(const float* __restrict__ Wi, const float* __restrict__ Wf,
                       const float* __restrict__ Wo, const float* __restrict__ Wz,
                       const float* __restrict__ bi, const float* __restrict__ bf,
                       const float* __restrict__ bo, const float* __restrict__ bz) {
    int idx = blockIdx.x * blockDim.x + threadIdx.x;
    if (idx < 456 * NJ) {
        int k = idx >> 10;
        int j = idx & (NJ - 1);
        int gate = j & 3;
        int c    = (j >> 2) & 31;
        int g    = j >> 7;
        int col  = g * 32 + c;
        const float* W = (gate == 0) ? Wi : (gate == 1) ? Wf : (gate == 2) ? Wo : Wz;
        float v = W[k * HH + col];
        if (k < DD) g_Wxp[k * NJ + j] = v;
        else        g_Whp[g * 32768 + (k - DD) * 128 + (j & 127)] = v;
    }
    if (idx < NJ) {
        int gate = idx & 3;
        int c    = (idx >> 2) & 31;
        int g    = idx >> 7;
        int col  = g * 32 + c;
        const float* bb = (gate == 0) ? bi : (gate == 1) ? bf : (gate == 2) ? bo : bz;
        g_biasp[idx] = bb[col];
    }
}

// ---------------- kernel 1: reset flags ----------------
__global__ void k_reset() {
    int i = threadIdx.x;
    if (i < 32) g_flags[i] = 0ull;
}

// ---------------- kernel 2: G = X @ Wxp + bias (EXACT R4/R10 version) ----------------
#define G1_BM 128
#define G1_BN 64
#define G1_BK 8
__global__ void __launch_bounds__(256) k_gemm1(const float* __restrict__ x) {
    __shared__ __align__(16) float As[2][G1_BK][G1_BM];
    __shared__ __align__(16) float Bs[2][G1_BK][G1_BN];

    int tid = threadIdx.x;
    int m0 = blockIdx.y * G1_BM;
    int n0 = blockIdx.x * G1_BN;

    int arow = tid >> 1;
    int akq  = (tid & 1) * 4;
    const float* aptr = x + (size_t)(m0 + arow) * DD + akq;

    int bkk = tid >> 5;
    int bn  = (tid & 31) * 2;
    const float* bptr = g_Wxp + (size_t)bkk * NJ + n0 + bn;

    int tx = tid & 15;   // 4 n-cols
    int ty = tid >> 4;   // 8 m-rows

    ull acc[4][4];
#pragma unroll
    for (int i = 0; i < 4; ++i)
#pragma unroll
        for (int j = 0; j < 4; ++j) acc[i][j] = 0ull;

    float4 av = *(const float4*)aptr;
    float2 bv = *(const float2*)bptr;
    As[0][akq + 0][arow] = av.x;
    As[0][akq + 1][arow] = av.y;
    As[0][akq + 2][arow] = av.z;
    As[0][akq + 3][arow] = av.w;
    *(float2*)&Bs[0][bkk][bn] = bv;

    for (int kc = 0; kc < 25; ++kc) {
        __syncthreads();
        int cur = kc & 1;
        if (kc < 24) {
            av = *(const float4*)(aptr + (kc + 1) * G1_BK);
            bv = *(const float2*)(bptr + (size_t)(kc + 1) * G1_BK * NJ);
        }
#pragma unroll
        for (int kk = 0; kk < G1_BK; ++kk) {
            const ull* ap2 = (const ull*)&As[cur][kk][ty * 8];
            ull A0 = ap2[0], A1 = ap2[1], A2 = ap2[2], A3 = ap2[3];
            float4 b4 = *(const float4*)&Bs[cur][kk][tx * 4];
            ull B0 = pk2(b4.x, b4.x), B1 = pk2(b4.y, b4.y);
            ull B2 = pk2(b4.z, b4.z), B3 = pk2(b4.w, b4.w);
            acc[0][0] = ffma2(A0, B0, acc[0][0]); acc[0][1] = ffma2(A0, B1, acc[0][1]);
            acc[0][2] = ffma2(A0, B2, acc[0][2]); acc[0][3] = ffma2(A0, B3, acc[0][3]);
            acc[1][0] = ffma2(A1, B0, acc[1][0]); acc[1][1] = ffma2(A1, B1, acc[1][1]);
            acc[1][2] = ffma2(A1, B2, acc[1][2]); acc[1][3] = ffma2(A1, B3, acc[1][3]);
            acc[2][0] = ffma2(A2, B0, acc[2][0]); acc[2][1] = ffma2(A2, B1, acc[2][1]);
            acc[2][2] = ffma2(A2, B2, acc[2][2]); acc[2][3] = ffma2(A2, B3, acc[2][3]);
            acc[3][0] = ffma2(A3, B0, acc[3][0]); acc[3][1] = ffma2(A3, B1, acc[3][1]);
            acc[3][2] = ffma2(A3, B2, acc[3][2]); acc[3][3] = ffma2(A3, B3, acc[3][3]);
        }
        if (kc < 24) {
            int nxt = cur ^ 1;
            As[nxt][akq + 0][arow] = av.x;
            As[nxt][akq + 1][arow] = av.y;
            As[nxt][akq + 2][arow] = av.z;
            As[nxt][akq + 3][arow] = av.w;
            *(float2*)&Bs[nxt][bkk][bn] = bv;
        }
    }

    float4 bias4 = *(const float4*)(g_biasp + n0 + tx * 4);
#pragma unroll
    for (int rp = 0; rp < 4; ++rp) {
        float4 r0, r1;
        upk2(acc[rp][0], r0.x, r1.x);
        upk2(acc[rp][1], r0.y, r1.y);
        upk2(acc[rp][2], r0.z, r1.z);
        upk2(acc[rp][3], r0.w, r1.w);
        r0.x += bias4.x; r0.y += bias4.y; r0.z += bias4.z; r0.w += bias4.w;
        r1.x += bias4.x; r1.y += bias4.y; r1.z += bias4.z; r1.w += bias4.w;
        size_t mrow = (size_t)m0 + ty * 8 + rp * 2;
        __stcs((float4*)(g_G + mrow * NJ + n0 + tx * 4), r0);
        __stcs((float4*)(g_G + (mrow + 1) * NJ + n0 + tx * 4), r1);
    }
}

// ---------------- kernel 3: persistent recurrence, pipelined slices ----------------
// R10 matvec body; h gathered in 2 phases of 4 producer-slices, phase B's LDG
// overlapped with phase A's matvec. One combined 8-field poll per step.
// smem: Ws 131072B + stage 2x8192B + ms 32768B = 180224B
#define REC_SMEM_BYTES (131072 + 16384 + 32768)
__global__ void __launch_bounds__(256, 1) k_rec(const float* __restrict__ mask,
                                                float* __restrict__ out) {
    extern __shared__ __align__(16) float sm[];
    float*  Ws  = sm;                        // [256 k][128 j]
    float4* stg = (float4*)(sm + 32768);     // [2 ph][4 sp][16 k2l][8 rp]
    float*  ms  = sm + 32768 + 4096;         // [512 s][16 r] mask transposed

    int tid = threadIdx.x;
    int grp = blockIdx.x >> 3;
    int g   = blockIdx.x & 7;
    int rp  = tid & 7;    // row pair: rows 2rp, 2rp+1
    int cq  = tid >> 3;   // hidden col in slice 0..31

    // preload weight slice (once for all 512 steps)
    {
        const float4* wsrc = (const float4*)(g_Whp + (size_t)g * 32768);
        float4* wdst = (float4*)Ws;
        for (int i = tid; i < 8192; i += 256) wdst[i] = wsrc[i];
    }
    // mask transpose: ms[s*16 + r]
    for (int i = tid; i < 8192; i += 256) {
        int r = i >> 9, s = i & 511;
        ms[s * 16 + r] = mask[(size_t)(grp * 16 + r) * SS + s];
    }
    __syncthreads();

    int b0 = grp * 16 + rp * 2;
    float c0 = 0.f, c1 = 0.f, sum0 = 0.f, sum1 = 0.f, msum0 = 0.f, msum1 = 0.f;
    const float* gbase = g_G + (size_t)b0 * SS * NJ + g * 128 + cq * 4;
    ull* flagw = &g_flags[grp * 2];
    ull  myinc = 1ull << (16 * (g & 3));
    int  myw   = g >> 2;

    // gather decode (constant per thread): entries e = tid, tid+256 per phase
    int e_sp[2], e_k2l[2], e_rp[2];
#pragma unroll
    for (int q = 0; q < 2; ++q) {
        int e = tid + q * 256;
        e_sp[q]  = e >> 7;
        e_k2l[q] = (e >> 3) & 15;
        e_rp[q]  = e & 7;
    }

    for (int s = 0; s < SS; ++s) {
        // prefetch this step's x-gate preactivations (independent of h)
        float4 ga = __ldcs((const float4*)(gbase + (size_t)s * NJ));
        float4 gb = __ldcs((const float4*)(gbase + (size_t)SS * NJ + (size_t)s * NJ));
        float2 mv = *(const float2*)&ms[s * 16 + rp * 2];

        ull a00 = pk2(ga.x, ga.y), a01 = pk2(ga.z, ga.w);
        ull a10 = pk2(gb.x, gb.y), a11 = pk2(gb.z, gb.w);

        if (s) {
            // one combined poll: all 8 producer fields >= s
            if (tid == 0) {
                unsigned us = (unsigned)s;
                for (;;) {
                    ull w0 = ldacq64(flagw);
                    ull w1 = ldacq64(flagw + 1);
                    if ((unsigned)(w0 & 0xFFFF) >= us &&
                        (unsigned)((w0 >> 16) & 0xFFFF) >= us &&
                        (unsigned)((w0 >> 32) & 0xFFFF) >= us &&
                        (unsigned)((w0 >> 48) & 0xFFFF) >= us &&
                        (unsigned)(w1 & 0xFFFF) >= us &&
                        (unsigned)((w1 >> 16) & 0xFFFF) >= us &&
                        (unsigned)((w1 >> 32) & 0xFFFF) >= us &&
                        (unsigned)((w1 >> 48) & 0xFFFF) >= us)
                        break;
                }
            }
            __syncthreads();

            // issue ALL gather LDGs (both phases) up front
            const float* hb = g_hbuf + ((size_t)(s & 1)) * 65536 + (size_t)grp * 4096;
            float2 va[4], vb[4];
            int    slot[4];
#pragma unroll
            for (int qq = 0; qq < 4; ++qq) {
                int q  = qq & 1;
                int ph = qq >> 1;
                int jj = (g + ph * 4 + e_sp[q]) & 7;
                const float* src = hb + ((jj * 32 + e_k2l[q] * 2) * 16 + e_rp[q] * 2);
                va[qq] = __ldcg((const float2*)src);
                vb[qq] = __ldcg((const float2*)(src + 16));
                slot[qq] = (ph << 9) + (e_sp[q] * 16 + e_k2l[q]) * 8 +
                           (e_rp[q] ^ (e_k2l[q] & 7));
            }

            // stage phase A, then matvec A while phase B's LDGs land
            stg[slot[0]] = make_float4(va[0].x, va[0].y, vb[0].x, vb[0].y);
            stg[slot[1]] = make_float4(va[1].x, va[1].y, vb[1].x, vb[1].y);
            __syncthreads();

            const ulonglong2* wq = (const ulonglong2*)Ws + cq;   // row k at +k*32
            for (int idx = 0; idx < 4; ++idx) {
                int jj = (g + idx) & 7;
                const ulonglong2* wj = wq + jj * 1024;
                const float4* hq = stg + idx * 128;
#pragma unroll 8
                for (int i = 0; i < 16; ++i) {
                    ulonglong2 w0 = wj[i * 64];
                    ulonglong2 w1 = wj[i * 64 + 32];
                    float4 h4 = hq[i * 8 + (rp ^ (i & 7))];
                    ull ha0 = pk2(h4.x, h4.x), hb0 = pk2(h4.y, h4.y);
                    ull ha1 = pk2(h4.z, h4.z), hb1 = pk2(h4.w, h4.w);
                    a00 = ffma2(ha0, w0.x, a00); a01 = ffma2(ha0, w0.y, a01);
                    a10 = ffma2(hb0, w0.x, a10); a11 = ffma2(hb0, w0.y, a11);
                    a00 = ffma2(ha1, w1.x, a00); a01 = ffma2(ha1, w1.y, a01);
                    a10 = ffma2(hb1, w1.x, a10); a11 = ffma2(hb1, w1.y, a11);
                }
            }

            // stage phase B, matvec B
            stg[slot[2]] = make_float4(va[2].x, va[2].y, vb[2].x, vb[2].y);
            stg[slot[3]] = make_float4(va[3].x, va[3].y, vb[3].x, vb[3].y);
            __syncthreads();

            for (int idx = 0; idx < 4; ++idx) {
                int jj = (g + 4 + idx) & 7;
                const ulonglong2* wj = wq + jj * 1024;
                const float4* hq = stg + 512 + idx * 128;
#pragma unroll 8
                for (int i = 0; i < 16; ++i) {
                    ulonglong2 w0 = wj[i * 64];
                    ulonglong2 w1 = wj[i * 64 + 32];
                    float4 h4 = hq[i * 8 + (rp ^ (i & 7))];
                    ull ha0 = pk2(h4.x, h4.x), hb0 = pk2(h4.y, h4.y);
                    ull ha1 = pk2(h4.z, h4.z), hb1 = pk2(h4.w, h4.w);
                    a00 = ffma2(ha0, w0.x, a00); a01 = ffma2(ha0, w0.y, a01);
                    a10 = ffma2(hb0, w0.x, a10); a11 = ffma2(hb0, w0.y, a11);
                    a00 = ffma2(ha1, w1.x, a00); a01 = ffma2(ha1, w1.y, a01);
                    a10 = ffma2(hb1, w1.x, a10); a11 = ffma2(hb1, w1.y, a11);
                }
            }
        }

        // nonlinearity + state update (gate order i,f,o,z)
        float ai0, af0, ao0, az0, ai1, af1, ao1, az1;
        upk2(a00, ai0, af0); upk2(a01, ao0, az0);
        upk2(a10, ai1, af1); upk2(a11, ao1, az1);
        float i0 = sigf(ai0), f0 = sigf(af0), o0 = sigf(ao0), z0 = tanhfast(az0);
        c0 = i0 * z0 + f0 * c0;
        float h0 = o0 * tanhfast(c0);
        float i1 = sigf(ai1), f1 = sigf(af1), o1 = sigf(ao1), z1 = tanhfast(az1);
        c1 = i1 * z1 + f1 * c1;
        float h1 = o1 * tanhfast(c1);
        sum0 += h0 * mv.x; msum0 += mv.x;
        sum1 += h1 * mv.y; msum1 += mv.y;

        // publish h[s+1]: [col][row] layout, one stcg.64 + packed flag release
        float2 hv; hv.x = h0; hv.y = h1;
        __stcg((float2*)(g_hbuf + ((size_t)((s + 1) & 1)) * 65536 + (size_t)grp * 4096 +
                         (size_t)(g * 32 + cq) * 16 + rp * 2),
               hv);
        __syncthreads();
        if (tid == 0) red_release64(&flagw[myw], myinc);
    }

    int hcol = g * 32 + cq;
    out[(size_t)b0 * HH + hcol]       = sum0 * __fdividef(1.0f, msum0);
    out[(size_t)(b0 + 1) * HH + hcol] = sum1 * __fdividef(1.0f, msum1);
}

// ---------------- launcher ----------------
extern "C" void kernel_launch(void* const* d_in, const int* in_sizes, int n_in,
                              void* d_out, int out_size) {
    const float* x    = (const float*)d_in[0];
    const float* mask = (const float*)d_in[1];
    const float* Wi   = (const float*)d_in[2];
    const float* bi   = (const float*)d_in[3];
    const float* Wf   = (const float*)d_in[4];
    const float* bf   = (const float*)d_in[5];
    const float* Wo   = (const float*)d_in[6];
    const float* bo   = (const float*)d_in[7];
    const float* Wz   = (const float*)d_in[8];
    const float* bz   = (const float*)d_in[9];
    float* out = (float*)d_out;

    cudaFuncSetAttribute(k_rec, cudaFuncAttributeMaxDynamicSharedMemorySize,
                         REC_SMEM_BYTES);

    k_pack<<<(456 * NJ + 255) / 256, 256>>>(Wi, Wf, Wo, Wz, bi, bf, bo, bz);
    k_reset<<<1, 32>>>();
    dim3 g1(NJ / G1_BN, (BB * SS) / G1_BM);
    k_gemm1<<<g1, 256>>>(x);
    k_rec<<<NGRP * NCOL, 256, REC_SMEM_BYTES>>>(mask, out);
}